// round 16
// baseline (speedup 1.0000x reference)
#include <cuda_runtime.h>

#define N_CLASS   10
#define PSTRIDE   12
#define MAX_NODES 100000

typedef unsigned long long ull;

__device__ __align__(16) float g_P[MAX_NODES * PSTRIDE];
__device__ __align__(16) float g_Q[MAX_NODES * PSTRIDE];

#define FFMA2(acc, a, b) \
    asm("fma.rn.f32x2 %0, %1, %2, %0;" : "+l"(acc) : "l"(a), "l"(b))
#define FMUL2(r, a, b) \
    asm("mul.rn.f32x2 %0, %1, %2;" : "=l"(r) : "l"(a), "l"(b))
#define FADD2(r, a, b) \
    asm("add.rn.f32x2 %0, %1, %2;" : "=l"(r) : "l"(a), "l"(b))

__device__ __forceinline__ ull pack2(float x, float y) {
    ull r;
    asm("mov.b64 %0, {%1, %2};" : "=l"(r) : "f"(x), "f"(y));
    return r;
}
__device__ __forceinline__ float2 unpack2(ull p) {
    float2 f;
    asm("mov.b64 {%0, %1}, %2;" : "=f"(f.x), "=f"(f.y) : "l"(p));
    return f;
}

// lane-resident weights: wp[p][k] = (W[2p][col], W[2p+1][col]) for this lane's 4 cols
__device__ __forceinline__ void load_weights(const float* __restrict__ W, int wcol,
                                             int lane, ull wp[5][4]) {
#pragma unroll
    for (int p = 0; p < 5; p++) {
        float4 wa = ((const float4*)(W + (2 * p) * 384 + wcol))[lane];
        float4 wb = ((const float4*)(W + (2 * p + 1) * 384 + wcol))[lane];
        wp[p][0] = pack2(wa.x, wb.x);
        wp[p][1] = pack2(wa.y, wb.y);
        wp[p][2] = pack2(wa.z, wb.z);
        wp[p][3] = pack2(wa.w, wb.w);
    }
}

// First step uses MUL (no zero-init), rest FMA.
__device__ __forceinline__ void dot10f(const ull wp[5][4], float4 v, ull acc[5]) {
    ull a0 = pack2(v.x, v.x);
    ull a1 = pack2(v.y, v.y);
    ull a2 = pack2(v.z, v.z);
    ull a3 = pack2(v.w, v.w);
#pragma unroll
    for (int p = 0; p < 5; p++) {
        FMUL2(acc[p], a0, wp[p][0]);
        FFMA2(acc[p], a1, wp[p][1]);
        FFMA2(acc[p], a2, wp[p][2]);
        FFMA2(acc[p], a3, wp[p][3]);
    }
}

// packed fold: dst = a + shfl_xor(b, m)   (5 u64 = 10 classes)
__device__ __forceinline__ void foldx(ull dst[5], const ull a[5], const ull b[5], int m) {
#pragma unroll
    for (int q = 0; q < 5; q++) {
        ull t = __shfl_xor_sync(0xffffffffu, b[q], m);
        FADD2(dst[q], a[q], t);
    }
}

// ---------------------------------------------------------------------------
// Fused node projection (unchanged R15 body): grid halves write g_P / g_Q.
// ---------------------------------------------------------------------------
__global__ __launch_bounds__(128)
void proj_kernel(const float* __restrict__ X, const float* __restrict__ W,
                 const float* __restrict__ bias, int n_rows) {
    int half = gridDim.x >> 1;
    int which = blockIdx.x >= half;
    int bx = which ? (blockIdx.x - half) : blockIdx.x;
    float* outbuf = which ? g_Q : g_P;
    int wcol = which ? 128 : 0;

    int lane = threadIdx.x & 31;
    int warp = (bx * blockDim.x + threadIdx.x) >> 5;
    int nwarps = (half * blockDim.x) >> 5;
    int o = lane >> 3, j = lane & 7;
    int k = ((o & 1) << 1) | (o >> 1);
    int kB = k ^ 1, kC = k ^ 2, kD = k ^ 3;
    int stride = nwarps * 4;

    ull wp[5][4];
    load_weights(W, wcol, lane, wp);

    float bb0 = 0.f, bb1 = 0.f, bb2 = 0.f, bb3 = 0.f;
    if (which == 0 && j < 3) {
        bb0 = __ldg(bias + j * 4);
        bb1 = __ldg(bias + j * 4 + 1);
        if (j < 2) { bb2 = __ldg(bias + j * 4 + 2); bb3 = __ldg(bias + j * 4 + 3); }
    }

    const float4* Xv = (const float4*)X;
    int nm1 = n_rows - 1;
    int base = warp * 4;
    if (base >= n_rows) return;

    float4 vA = Xv[(size_t)min(base + k, nm1) * 32 + lane];
    float4 vB = Xv[(size_t)min(base + kB, nm1) * 32 + lane];
    float4 vC = Xv[(size_t)min(base + kC, nm1) * 32 + lane];
    float4 vD = Xv[(size_t)min(base + kD, nm1) * 32 + lane];

    while (true) {
        int nb = base + stride;
        bool has_next = nb < n_rows;
        float4 nA, nB, nC, nD;
        if (has_next) {
            nA = Xv[(size_t)min(nb + k, nm1) * 32 + lane];
            nB = Xv[(size_t)min(nb + kB, nm1) * 32 + lane];
            nC = Xv[(size_t)min(nb + kC, nm1) * 32 + lane];
            nD = Xv[(size_t)min(nb + kD, nm1) * 32 + lane];
        }

        ull aA[5], aB[5], aC[5], aD[5];
        dot10f(wp, vA, aA);
        dot10f(wp, vB, aB);
        dot10f(wp, vC, aC);
        dot10f(wp, vD, aD);

        float pA[N_CLASS], pB[N_CLASS], pC[N_CLASS], pD[N_CLASS];
#pragma unroll
        for (int q = 0; q < 5; q++) {
            float2 f;
            f = unpack2(aA[q]); pA[2 * q] = f.x; pA[2 * q + 1] = f.y;
            f = unpack2(aB[q]); pB[2 * q] = f.x; pB[2 * q + 1] = f.y;
            f = unpack2(aC[q]); pC[2 * q] = f.x; pC[2 * q + 1] = f.y;
            f = unpack2(aD[q]); pD[2 * q] = f.x; pD[2 * q + 1] = f.y;
        }
        float u[N_CLASS];
#pragma unroll
        for (int c = 0; c < N_CLASS; c++) {
            float t  = pA[c] + __shfl_xor_sync(0xffffffffu, pB[c], 16);
            float t2 = pC[c] + __shfl_xor_sync(0xffffffffu, pD[c], 16);
            float w  = t + __shfl_xor_sync(0xffffffffu, t2, 8);
            w += __shfl_xor_sync(0xffffffffu, w, 4);
            w += __shfl_xor_sync(0xffffffffu, w, 2);
            w += __shfl_xor_sync(0xffffffffu, w, 1);
            u[c] = w;
        }

        int ridx = base + k;
        if (ridx < n_rows && j < 3) {
            float4* O = (float4*)(outbuf + (size_t)ridx * PSTRIDE);
            if (j == 0)      O[0] = make_float4(u[0] + bb0, u[1] + bb1, u[2] + bb2, u[3] + bb3);
            else if (j == 1) O[1] = make_float4(u[4] + bb0, u[5] + bb1, u[6] + bb2, u[7] + bb3);
            else             O[2] = make_float4(u[8] + bb0, u[9] + bb1, 0.f, 0.f);
        }

        if (!has_next) break;
        base = nb;
        vA = nA; vB = nB; vC = nC; vD = nD;
    }
}

// ---------------------------------------------------------------------------
// Edge kernel: 8 edges per warp pass. Slot s of lane l holds edge
// base + (perm(l)^s), perm = bitrev(lane bits 4,3,2). Packed tree folds
// interleaved with dots; packed epilogue; P/Q gathered at top of pass.
// ---------------------------------------------------------------------------
__global__ __launch_bounds__(128)
void edge_score_kernel(const float* __restrict__ eh, const float* __restrict__ W,
                       const int* __restrict__ src, const int* __restrict__ dst,
                       float* __restrict__ out, int n_edges) {
    int lane = threadIdx.x & 31;
    int warp = (blockIdx.x * blockDim.x + threadIdx.x) >> 5;
    int nwarps = (gridDim.x * blockDim.x) >> 5;
    int perm = ((lane >> 4) & 1) | (((lane >> 3) & 1) << 1) | (((lane >> 2) & 1) << 2);
    int j2 = lane & 3;
    int stride = nwarps * 8;

    ull wp[5][4];
    load_weights(W, 256, lane, wp);

    const float4* Ev = (const float4*)eh;
    int nm1 = n_edges - 1;
    int base = warp * 8;
    if (base >= n_edges) return;

    int s, d;
    {
        int ce = min(base + perm, nm1);
        s = src[ce]; d = dst[ce];
    }

    while (true) {
        // 8 coalesced row loads (MLP=8)
        float4 v0 = Ev[(size_t)min(base + (perm ^ 0), nm1) * 32 + lane];
        float4 v1 = Ev[(size_t)min(base + (perm ^ 1), nm1) * 32 + lane];
        float4 v2 = Ev[(size_t)min(base + (perm ^ 2), nm1) * 32 + lane];
        float4 v3 = Ev[(size_t)min(base + (perm ^ 3), nm1) * 32 + lane];
        float4 v4 = Ev[(size_t)min(base + (perm ^ 4), nm1) * 32 + lane];
        float4 v5 = Ev[(size_t)min(base + (perm ^ 5), nm1) * 32 + lane];
        float4 v6 = Ev[(size_t)min(base + (perm ^ 6), nm1) * 32 + lane];
        float4 v7 = Ev[(size_t)min(base + (perm ^ 7), nm1) * 32 + lane];

        // P/Q gather for this pass's edge, issued early (hidden under dots)
        ulonglong2 Pv, Qv;
        if (j2 < 3) {
            Pv = *(const ulonglong2*)(g_P + (size_t)s * PSTRIDE + 4 * j2);
            Qv = *(const ulonglong2*)(g_Q + (size_t)d * PSTRIDE + 4 * j2);
        }

        // prefetch next pass's indices
        int nb = base + stride;
        bool has_next = nb < n_edges;
        int ns = 0, nd = 0;
        if (has_next) {
            int ne = min(nb + perm, nm1);
            ns = src[ne]; nd = dst[ne];
        }

        // dots + interleaved packed folds
        ull F0123[5], F4567[5], F[5];
        {
            ull a0[5], a1[5], F01[5], F23[5];
            dot10f(wp, v0, a0);
            dot10f(wp, v1, a1);
            foldx(F01, a0, a1, 16);
            dot10f(wp, v2, a0);
            dot10f(wp, v3, a1);
            foldx(F23, a0, a1, 16);
            foldx(F0123, F01, F23, 8);
            dot10f(wp, v4, a0);
            dot10f(wp, v5, a1);
            foldx(F01, a0, a1, 16);
            dot10f(wp, v6, a0);
            dot10f(wp, v7, a1);
            foldx(F23, a0, a1, 16);
            foldx(F4567, F01, F23, 8);
        }
        foldx(F, F0123, F4567, 4);
        foldx(F, F, F, 2);
        foldx(F, F, F, 1);

        // packed epilogue: quad lanes j2<3 store slices of edge base+perm
        int eidx = base + perm;
        if (eidx < n_edges && j2 < 3) {
            ull* ob = (ull*)(out + (size_t)eidx * N_CLASS);
            if (j2 == 0) {
                ull r0, r1;
                FADD2(r0, F[0], Pv.x); FADD2(r0, r0, Qv.x);
                FADD2(r1, F[1], Pv.y); FADD2(r1, r1, Qv.y);
                ob[0] = r0; ob[1] = r1;
            } else if (j2 == 1) {
                ull r0, r1;
                FADD2(r0, F[2], Pv.x); FADD2(r0, r0, Qv.x);
                FADD2(r1, F[3], Pv.y); FADD2(r1, r1, Qv.y);
                ob[2] = r0; ob[3] = r1;
            } else {
                ull r0;
                FADD2(r0, F[4], Pv.x); FADD2(r0, r0, Qv.x);
                ob[4] = r0;
            }
        }

        if (!has_next) break;
        base = nb;
        s = ns; d = nd;
    }
}

// ---------------------------------------------------------------------------
extern "C" void kernel_launch(void* const* d_in, const int* in_sizes, int n_in,
                              void* d_out, int out_size) {
    const float* h   = (const float*)d_in[0];
    const float* eh  = (const float*)d_in[1];
    const float* W   = (const float*)d_in[2];
    const float* b   = (const float*)d_in[3];
    const int*   src = (const int*)d_in[4];
    const int*   dst = (const int*)d_in[5];
    float*       out = (float*)d_out;

    int n_nodes = in_sizes[0] / 128;
    int n_edges = in_sizes[4];

    proj_kernel<<<1184, 128>>>(h, W, b, n_nodes);          // halves: g_P | g_Q
    edge_score_kernel<<<1184, 128>>>(eh, W, src, dst, out, n_edges);
}